// round 13
// baseline (speedup 1.0000x reference)
#include <cuda_runtime.h>
#include <cuda_fp16.h>

#define B_    64
#define P_    196
#define E_    2048
#define H_    512
#define EMB_  512
#define V_    10000
#define TCAP  50
#define TMAX  49
#define MP_   (B_*P_)            /* 12544 */

#define PRED_SZ  ((size_t)B_*TCAP*V_)   /* 32,000,000 */
#define ALPHA_SZ ((size_t)B_*TCAP*P_)   /* 627,200 */

#define NB3H  ((3*H_)/64)        /* 24 N-blocks (64 cols) for GRU gate GEMMs */
#define GI_SPLITS 4
#define GI_KCHUNK ((E_+EMB_)/GI_SPLITS)   /* 640 */
#define PREDB ((V_ + 63)/64)     /* 157 pred N-blocks */
#define LAM_RPB 7                /* p-rows per k_lam block; 196 = 28*7 */
#define LAM_BPB 28               /* k_lam blocks per batch row */

// ---------------- scratch (device globals; no allocation allowed) ----------
__device__ __half g_xwx[(size_t)MP_*E_];    // ~51.5 MB (fp16)
__device__ __half g_feat16[(size_t)MP_*E_]; // ~51.5 MB (fp16 copy of features)
__device__ float g_fmean[B_*E_];
__device__ float g_h[B_*H_];
__device__ float g_hwh[B_*E_];
__device__ float g_lam[B_*P_];
__device__ float g_z[B_*E_];
__device__ float g_gate[B_*E_];
__device__ float g_gip[GI_SPLITS][B_*3*H_];  // split-K partials for gi (no bias)
__device__ float g_gh[B_*3*H_];              // gh partial (no bias)

// ---------------- fast math ------------------------------------------------
__device__ __forceinline__ float ftanh(float x) {
    float y;
    asm("tanh.approx.f32 %0, %1;" : "=f"(y) : "f"(x));
    return y;
}
__device__ __forceinline__ float fsig(float x) {
    return 1.f / (1.f + __expf(-x));
}
__device__ __forceinline__ unsigned int f2tf32(float x) {
    unsigned int u;
    asm("cvt.rna.tf32.f32 %0, %1;" : "=r"(u) : "f"(x));
    return u;
}
__device__ __forceinline__ float4 tf32x4(float4 v) {
    v.x = __uint_as_float(f2tf32(v.x));
    v.y = __uint_as_float(f2tf32(v.y));
    v.z = __uint_as_float(f2tf32(v.z));
    v.w = __uint_as_float(f2tf32(v.w));
    return v;
}
#define MMA_TF32(acc, af, bf)                                                  \
    asm volatile(                                                              \
        "mma.sync.aligned.m16n8k8.row.col.f32.tf32.tf32.f32 "                  \
        "{%0,%1,%2,%3}, {%4,%5,%6,%7}, {%8,%9}, {%0,%1,%2,%3};"                \
        : "+f"((acc)[0]), "+f"((acc)[1]), "+f"((acc)[2]), "+f"((acc)[3])       \
        : "r"((af)[0]), "r"((af)[1]), "r"((af)[2]), "r"((af)[3]),              \
          "r"((bf)[0]), "r"((bf)[1]))

// ---------------- zero output + write dec ----------------------------------
__global__ void k_zero(float* out, const int* lengths) {
    size_t n = PRED_SZ + ALPHA_SZ;
    size_t i = (size_t)blockIdx.x * blockDim.x + threadIdx.x;
    size_t stride = (size_t)gridDim.x * blockDim.x;
    for (size_t j = i; j < n; j += stride) out[j] = 0.f;
    if (i < B_) out[PRED_SZ + ALPHA_SZ + i] = (float)(lengths[i] - 1);
}

// ---------------- features -> fp16 copy ------------------------------------
__global__ void k_feat16(const float* __restrict__ feat) {
    size_t i = (size_t)blockIdx.x * 256 + threadIdx.x;   // over MP_*E_/4
    float4 v = ((const float4*)feat)[i];
    __half2 a = __floats2half2_rn(v.x, v.y);
    __half2 b = __floats2half2_rn(v.z, v.w);
    uint2 u;
    u.x = *(unsigned int*)&a;
    u.y = *(unsigned int*)&b;
    ((uint2*)g_feat16)[i] = u;
}

// ---------------- feature mean over P (float4) -----------------------------
__global__ void k_fmean(const float* __restrict__ feat) {
    int i = blockIdx.x * 256 + threadIdx.x;   // over B*E/4
    int b = i / (E_/4), e4 = i % (E_/4);
    const float4* fp = (const float4*)(feat + (size_t)b * P_ * E_) + e4;
    float4 s = make_float4(0.f, 0.f, 0.f, 0.f);
    #pragma unroll 4
    for (int p = 0; p < P_; p++) {
        float4 v = fp[(size_t)p * (E_/4)];
        s.x += v.x; s.y += v.y; s.z += v.z; s.w += v.w;
    }
    const float inv = 1.f / P_;
    s.x *= inv; s.y *= inv; s.z *= inv; s.w *= inv;
    ((float4*)g_fmean)[i] = s;
}

// ---------------- tf32 tensor-core GEMM: xwx(half) = A @ W^T + bias --------
// 128x128 tile, BK=16, 8 warps (2M x 4N), warp tile 64x32. (proven)
__global__ void __launch_bounds__(256, 2)
k_gemm_tc(const float* __restrict__ A, const float* __restrict__ W,
          const float* __restrict__ bias, __half* __restrict__ C,
          int N, int K) {
    __shared__ __align__(16) float As[2][128][20];
    __shared__ __align__(16) float Ws[2][128][20];
    int tid = threadIdx.x;
    int m0 = blockIdx.y * 128, n0 = blockIdx.x * 128;
    int lr = tid >> 2;
    int lk = (tid & 3) * 4;
    int wid  = tid >> 5;
    int lane = tid & 31;
    int wm = wid & 1;
    int wn = wid >> 1;
    int g = lane >> 2, u = lane & 3;

    float acc[4][4][4] = {};

    #pragma unroll
    for (int r = 0; r < 2; r++) {
        int row = lr + r * 64;
        float4 v = tf32x4(*(const float4*)&A[(size_t)(m0 + row) * K + lk]);
        As[0][row][lk+0] = v.x; As[0][row][lk+1] = v.y; As[0][row][lk+2] = v.z; As[0][row][lk+3] = v.w;
        float4 w = tf32x4(*(const float4*)&W[(size_t)(n0 + row) * K + lk]);
        Ws[0][row][lk+0] = w.x; Ws[0][row][lk+1] = w.y; Ws[0][row][lk+2] = w.z; Ws[0][row][lk+3] = w.w;
    }
    __syncthreads();

    int buf = 0;
    for (int k0 = 0; k0 < K; k0 += 16) {
        bool more = (k0 + 16) < K;
        float4 pv[2], pw[2];
        if (more) {
            #pragma unroll
            for (int r = 0; r < 2; r++) {
                int row = lr + r * 64;
                pv[r] = *(const float4*)&A[(size_t)(m0 + row) * K + k0 + 16 + lk];
                pw[r] = *(const float4*)&W[(size_t)(n0 + row) * K + k0 + 16 + lk];
            }
        }
        #pragma unroll
        for (int ks = 0; ks < 16; ks += 8) {
            unsigned int af[4][4], bf[4][2];
            #pragma unroll
            for (int mt = 0; mt < 4; mt++) {
                int mb = wm * 64 + mt * 16;
                af[mt][0] = __float_as_uint(As[buf][mb + g    ][ks + u    ]);
                af[mt][1] = __float_as_uint(As[buf][mb + g + 8][ks + u    ]);
                af[mt][2] = __float_as_uint(As[buf][mb + g    ][ks + u + 4]);
                af[mt][3] = __float_as_uint(As[buf][mb + g + 8][ks + u + 4]);
            }
            #pragma unroll
            for (int nt = 0; nt < 4; nt++) {
                int nb = wn * 32 + nt * 8;
                bf[nt][0] = __float_as_uint(Ws[buf][nb + g][ks + u    ]);
                bf[nt][1] = __float_as_uint(Ws[buf][nb + g][ks + u + 4]);
            }
            #pragma unroll
            for (int mt = 0; mt < 4; mt++)
                #pragma unroll
                for (int nt = 0; nt < 4; nt++)
                    MMA_TF32(acc[mt][nt], af[mt], bf[nt]);
        }
        if (more) {
            int nb = buf ^ 1;
            #pragma unroll
            for (int r = 0; r < 2; r++) {
                int row = lr + r * 64;
                float4 v = tf32x4(pv[r]);
                As[nb][row][lk+0] = v.x; As[nb][row][lk+1] = v.y; As[nb][row][lk+2] = v.z; As[nb][row][lk+3] = v.w;
                float4 w = tf32x4(pw[r]);
                Ws[nb][row][lk+0] = w.x; Ws[nb][row][lk+1] = w.y; Ws[nb][row][lk+2] = w.z; Ws[nb][row][lk+3] = w.w;
            }
            __syncthreads();
            buf = nb;
        }
    }

    #pragma unroll
    for (int mt = 0; mt < 4; mt++) {
        #pragma unroll
        for (int nt = 0; nt < 4; nt++) {
            int m = m0 + wm * 64 + mt * 16 + g;
            int n = n0 + wn * 32 + nt * 8 + u * 2;
            float b0 = bias[n], b1 = bias[n + 1];
            __half2 h0 = __floats2half2_rn(acc[mt][nt][0] + b0, acc[mt][nt][1] + b1);
            *(__half2*)&C[(size_t)m * N + n] = h0;
            __half2 h1 = __floats2half2_rn(acc[mt][nt][2] + b0, acc[mt][nt][3] + b1);
            *(__half2*)&C[(size_t)(m + 8) * N + n] = h1;
        }
    }
}

// ---------------- tf32 TC skinny GEMM core (shared mem passed in) ----------
// M=64, one 64-col N tile at n0, BK=32, 8 warps as 2(M)x4(N), warp tile 32x16.
// bias may be nullptr (no bias).
__device__ __forceinline__ void tc64_core(
    float (&As)[2][64][36], float (&Ws)[2][64][36],
    const float* __restrict__ A, const float* __restrict__ W,
    const float* __restrict__ bias, float* __restrict__ C,
    int N, int K, int ldc, int act,
    const int* __restrict__ lengths, int t, int n0) {
    int tid = threadIdx.x;
    int row = tid >> 2;            // 0..63
    int lk8 = (tid & 3) * 8;       // 0,8,16,24
    int wid = tid >> 5, lane = tid & 31;
    int wm = wid & 1, wn = wid >> 1;
    int g = lane >> 2, u = lane & 3;
    int wrow = n0 + row; if (wrow >= N) wrow = N - 1;   // clamp (tail tile)

    float acc[2][2][4] = {};
    float4 pa0, pa1, pw0, pw1;

    pa0 = *(const float4*)&A[(size_t)row * K + lk8];
    pa1 = *(const float4*)&A[(size_t)row * K + lk8 + 4];
    pw0 = *(const float4*)&W[(size_t)wrow * K + lk8];
    pw1 = *(const float4*)&W[(size_t)wrow * K + lk8 + 4];
    *(float4*)&As[0][row][lk8]     = tf32x4(pa0);
    *(float4*)&As[0][row][lk8 + 4] = tf32x4(pa1);
    *(float4*)&Ws[0][row][lk8]     = tf32x4(pw0);
    *(float4*)&Ws[0][row][lk8 + 4] = tf32x4(pw1);
    __syncthreads();

    int buf = 0;
    for (int k0 = 0; k0 < K; k0 += 32) {
        bool more = (k0 + 32) < K;
        if (more) {
            pa0 = *(const float4*)&A[(size_t)row * K + k0 + 32 + lk8];
            pa1 = *(const float4*)&A[(size_t)row * K + k0 + 32 + lk8 + 4];
            pw0 = *(const float4*)&W[(size_t)wrow * K + k0 + 32 + lk8];
            pw1 = *(const float4*)&W[(size_t)wrow * K + k0 + 32 + lk8 + 4];
        }
        #pragma unroll
        for (int ks = 0; ks < 32; ks += 8) {
            unsigned int af[2][4], bf[2][2];
            #pragma unroll
            for (int mt = 0; mt < 2; mt++) {
                int mb = wm * 32 + mt * 16;
                af[mt][0] = __float_as_uint(As[buf][mb + g    ][ks + u    ]);
                af[mt][1] = __float_as_uint(As[buf][mb + g + 8][ks + u    ]);
                af[mt][2] = __float_as_uint(As[buf][mb + g    ][ks + u + 4]);
                af[mt][3] = __float_as_uint(As[buf][mb + g + 8][ks + u + 4]);
            }
            #pragma unroll
            for (int nt = 0; nt < 2; nt++) {
                int nb = wn * 16 + nt * 8;
                bf[nt][0] = __float_as_uint(Ws[buf][nb + g][ks + u    ]);
                bf[nt][1] = __float_as_uint(Ws[buf][nb + g][ks + u + 4]);
            }
            #pragma unroll
            for (int mt = 0; mt < 2; mt++)
                #pragma unroll
                for (int nt = 0; nt < 2; nt++)
                    MMA_TF32(acc[mt][nt], af[mt], bf[nt]);
        }
        if (more) {
            buf ^= 1;
            *(float4*)&As[buf][row][lk8]     = tf32x4(pa0);
            *(float4*)&As[buf][row][lk8 + 4] = tf32x4(pa1);
            *(float4*)&Ws[buf][row][lk8]     = tf32x4(pw0);
            *(float4*)&Ws[buf][row][lk8 + 4] = tf32x4(pw1);
            __syncthreads();
        }
    }

    #pragma unroll
    for (int mt = 0; mt < 2; mt++) {
        int m = wm * 32 + mt * 16 + g;
        bool ok0 = !lengths || (lengths[m] - 1 >= t);
        bool ok1 = !lengths || (lengths[m + 8] - 1 >= t);
        #pragma unroll
        for (int nt = 0; nt < 2; nt++) {
            int n = n0 + wn * 16 + nt * 8 + u * 2;
            float b0 = (bias && n     < N) ? bias[n]     : 0.f;
            float b1 = (bias && n + 1 < N) ? bias[n + 1] : 0.f;
            float v0 = acc[mt][nt][0] + b0, v1 = acc[mt][nt][1] + b1;
            float v2 = acc[mt][nt][2] + b0, v3 = acc[mt][nt][3] + b1;
            if (act == 1) { v0 = fsig(v0); v1 = fsig(v1); v2 = fsig(v2); v3 = fsig(v3); }
            if (ok0) {
                if (n     < N) C[(size_t)m * ldc + n]     = v0;
                if (n + 1 < N) C[(size_t)m * ldc + n + 1] = v1;
            }
            if (ok1) {
                if (n     < N) C[(size_t)(m + 8) * ldc + n]     = v2;
                if (n + 1 < N) C[(size_t)(m + 8) * ldc + n + 1] = v3;
            }
        }
    }
}

// ---------------- standalone skinny GEMM (h0) -------------------------------
__global__ void __launch_bounds__(256)
k_tc64(const float* __restrict__ A, const float* __restrict__ W,
       const float* __restrict__ bias, float* __restrict__ C,
       int N, int K, int ldc, int act,
       const int* __restrict__ lengths, int t) {
    __shared__ __align__(16) float As[2][64][36];
    __shared__ __align__(16) float Ws[2][64][36];
    tc64_core(As, Ws, A, W, bias, C, N, K, ldc, act, lengths, t, blockIdx.x * 64);
}

// ---------------- fused post-GRU GEMMs ------------------------------------
// blocks [0, predb): pred (masked)
// then 32 blocks: h_wh | 32 blocks: gate(sigmoid) | 24 blocks: gh (no bias)
// Pre-loop: predb = 0 (grid 88). In-loop: predb = PREDB (grid 245+24=269... PREDB+88).
__global__ void __launch_bounds__(256)
k_step_fused(const float* __restrict__ fc1_w, const float* __restrict__ fc1_b,
             float* __restrict__ out_pred,
             const float* __restrict__ Wh_w, const float* __restrict__ Wh_b,
             const float* __restrict__ fb_w, const float* __restrict__ fb_b,
             const float* __restrict__ w_hh,
             const int* __restrict__ lengths, int t, int predb) {
    __shared__ __align__(16) float As[2][64][36];
    __shared__ __align__(16) float Ws[2][64][36];
    int blk = blockIdx.x;
    if (blk < predb) {
        tc64_core(As, Ws, g_h, fc1_w, fc1_b, out_pred,
                  V_, H_, TCAP * V_, 0, lengths, t, blk * 64);
        return;
    }
    int r = blk - predb;
    if (r < E_/64) {
        tc64_core(As, Ws, g_h, Wh_w, Wh_b, g_hwh,
                  E_, H_, E_, 0, nullptr, 0, r * 64);
    } else if (r < 2*(E_/64)) {
        tc64_core(As, Ws, g_h, fb_w, fb_b, g_gate,
                  E_, H_, E_, 1, nullptr, 0, (r - E_/64) * 64);
    } else {
        tc64_core(As, Ws, g_h, w_hh, nullptr, g_gh,
                  3*H_, H_, 3*H_, 0, nullptr, 0, (r - 2*(E_/64)) * 64);
    }
}

// ---------------- TC gi GEMM: split-K x4 (96 blocks) ------------------------
__global__ void __launch_bounds__(256)
k_gates_tc(const float* __restrict__ w_ih,
           const float* __restrict__ embed, const int* __restrict__ captions,
           int t) {
    int blk = blockIdx.x;
    int s     = blk / NB3H;
    int n0    = (blk % NB3H) * 64;
    int kbase = s * GI_KCHUNK;
    const int Kfull = E_ + EMB_;
    float* C = g_gip[s];

    __shared__ __align__(16) float As[2][64][36];
    __shared__ __align__(16) float Ws[2][64][36];
    int tid = threadIdx.x;
    int row = tid >> 2;
    int lk8 = (tid & 3) * 8;
    int wid = tid >> 5, lane = tid & 31;
    int wm = wid & 1, wn = wid >> 1;
    int g = lane >> 2, u = lane & 3;

    float acc[2][2][4] = {};
    float4 pa0, pa1, pw0, pw1;

    #define FETCH_A4(kg, dst) do {                                            \
        if ((kg) < E_) {                                                      \
            float4 gg = *(const float4*)&g_gate[(size_t)row * E_ + (kg)];     \
            float4 zz = *(const float4*)&g_z[(size_t)row * E_ + (kg)];        \
            dst = make_float4(gg.x*zz.x, gg.y*zz.y, gg.z*zz.z, gg.w*zz.w);    \
        } else {                                                              \
            int cap = captions[row * TCAP + t];                               \
            dst = *(const float4*)&embed[(size_t)cap * EMB_ + ((kg) - E_)];   \
        }                                                                     \
    } while (0)

    FETCH_A4(kbase + lk8,     pa0);
    FETCH_A4(kbase + lk8 + 4, pa1);
    pw0 = *(const float4*)&w_ih[(size_t)(n0 + row) * Kfull + kbase + lk8];
    pw1 = *(const float4*)&w_ih[(size_t)(n0 + row) * Kfull + kbase + lk8 + 4];
    *(float4*)&As[0][row][lk8]     = tf32x4(pa0);
    *(float4*)&As[0][row][lk8 + 4] = tf32x4(pa1);
    *(float4*)&Ws[0][row][lk8]     = tf32x4(pw0);
    *(float4*)&Ws[0][row][lk8 + 4] = tf32x4(pw1);
    __syncthreads();

    int buf = 0;
    for (int k0 = 0; k0 < GI_KCHUNK; k0 += 32) {
        bool more = (k0 + 32) < GI_KCHUNK;
        if (more) {
            int kg = kbase + k0 + 32 + lk8;
            FETCH_A4(kg,     pa0);
            FETCH_A4(kg + 4, pa1);
            pw0 = *(const float4*)&w_ih[(size_t)(n0 + row) * Kfull + kg];
            pw1 = *(const float4*)&w_ih[(size_t)(n0 + row) * Kfull + kg + 4];
        }
        #pragma unroll
        for (int ks = 0; ks < 32; ks += 8) {
            unsigned int af[2][4], bf[2][2];
            #pragma unroll
            for (int mt = 0; mt < 2; mt++) {
                int mb = wm * 32 + mt * 16;
                af[mt][0] = __float_as_uint(As[buf][mb + g    ][ks + u    ]);
                af[mt][1] = __float_as_uint(As[buf][mb + g + 8][ks + u    ]);
                af[mt][2] = __float_as_uint(As[buf][mb + g    ][ks + u + 4]);
                af[mt][3] = __float_as_uint(As[buf][mb + g + 8][ks + u + 4]);
            }
            #pragma unroll
            for (int nt = 0; nt < 2; nt++) {
                int nb = wn * 16 + nt * 8;
                bf[nt][0] = __float_as_uint(Ws[buf][nb + g][ks + u    ]);
                bf[nt][1] = __float_as_uint(Ws[buf][nb + g][ks + u + 4]);
            }
            #pragma unroll
            for (int mt = 0; mt < 2; mt++)
                #pragma unroll
                for (int nt = 0; nt < 2; nt++)
                    MMA_TF32(acc[mt][nt], af[mt], bf[nt]);
        }
        if (more) {
            buf ^= 1;
            *(float4*)&As[buf][row][lk8]     = tf32x4(pa0);
            *(float4*)&As[buf][row][lk8 + 4] = tf32x4(pa1);
            *(float4*)&Ws[buf][row][lk8]     = tf32x4(pw0);
            *(float4*)&Ws[buf][row][lk8 + 4] = tf32x4(pw1);
            __syncthreads();
        }
    }
    #undef FETCH_A4

    #pragma unroll
    for (int mt = 0; mt < 2; mt++) {
        int m = wm * 32 + mt * 16 + g;
        #pragma unroll
        for (int nt = 0; nt < 2; nt++) {
            int n = n0 + wn * 16 + nt * 8 + u * 2;
            C[(size_t)m * (3*H_) + n]           = acc[mt][nt][0];
            C[(size_t)m * (3*H_) + n + 1]       = acc[mt][nt][1];
            C[(size_t)(m + 8) * (3*H_) + n]     = acc[mt][nt][2];
            C[(size_t)(m + 8) * (3*H_) + n + 1] = acc[mt][nt][3];
        }
    }
}

// ---------------- attention: lam[b,p] = V . tanh(xwx16[b,p]+h_wh[b]) + Vb --
// 28 blocks per batch row, 7 p-rows per block; h_wh and V staged in smem.
__global__ void __launch_bounds__(256)
k_lam(const float* __restrict__ Vw, const float* __restrict__ Vb) {
    __shared__ float sh_h[E_];
    __shared__ float sh_v[E_];
    __shared__ float red[8];
    int b  = blockIdx.x / LAM_BPB;
    int p0 = (blockIdx.x % LAM_BPB) * LAM_RPB;
    int tid = threadIdx.x;
    int lane = tid & 31, w = tid >> 5;

    const float4* hw4 = (const float4*)(g_hwh + (size_t)b * E_);
    const float4* vw4 = (const float4*)Vw;
    #pragma unroll
    for (int i = tid; i < E_/4; i += 256) {
        ((float4*)sh_h)[i] = hw4[i];
        ((float4*)sh_v)[i] = vw4[i];
    }
    __syncthreads();

    float vb = Vb[0];
    for (int r = 0; r < LAM_RPB; r++) {
        int bp = b * P_ + p0 + r;
        const uint2* xw2 = (const uint2*)(g_xwx + (size_t)bp * E_);
        float s = 0.f;
        #pragma unroll
        for (int q = 0; q < 2; q++) {
            int i = tid * 2 + q;              // float4-granule index 0..511
            uint2 uu = xw2[i];
            float2 fa = __half22float2(*(__half2*)&uu.x);
            float2 fb = __half22float2(*(__half2*)&uu.y);
            int e = i * 4;
            s += ftanh(fa.x + sh_h[e+0]) * sh_v[e+0]
               + ftanh(fa.y + sh_h[e+1]) * sh_v[e+1]
               + ftanh(fb.x + sh_h[e+2]) * sh_v[e+2]
               + ftanh(fb.y + sh_h[e+3]) * sh_v[e+3];
        }
        #pragma unroll
        for (int o = 16; o > 0; o >>= 1) s += __shfl_xor_sync(0xffffffffu, s, o);
        if (lane == 0) red[w] = s;
        __syncthreads();
        if (tid == 0) {
            float tot = 0.f;
            #pragma unroll
            for (int i = 0; i < 8; i++) tot += red[i];
            g_lam[bp] = tot + vb;
        }
        __syncthreads();
    }
}

// ---------------- fused softmax + z (4 e-quarters per batch, 128 thr) ------
__global__ void __launch_bounds__(128)
k_z(float* __restrict__ out_alphas, const int* __restrict__ lengths, int t) {
    int b     = blockIdx.x >> 2;
    int chunk = blockIdx.x & 3;
    int tid = threadIdx.x;
    int lane = tid & 31, w = tid >> 5;
    __shared__ float red[4];
    __shared__ float bmax, bsum;
    __shared__ float al[P_];

    // softmax over P=196 with 128 threads: elements tid and tid+128
    float v0 = (tid < P_)       ? g_lam[b * P_ + tid]       : -3.4e38f;
    float v1 = (tid + 128 < P_) ? g_lam[b * P_ + tid + 128] : -3.4e38f;
    float m = fmaxf(v0, v1);
    #pragma unroll
    for (int o = 16; o > 0; o >>= 1) m = fmaxf(m, __shfl_xor_sync(0xffffffffu, m, o));
    if (lane == 0) red[w] = m;
    __syncthreads();
    if (tid == 0) {
        float mm = fmaxf(fmaxf(red[0], red[1]), fmaxf(red[2], red[3]));
        bmax = mm;
    }
    __syncthreads();
    float ex0 = (tid < P_)       ? __expf(v0 - bmax) : 0.f;
    float ex1 = (tid + 128 < P_) ? __expf(v1 - bmax) : 0.f;
    float s = ex0 + ex1;
    #pragma unroll
    for (int o = 16; o > 0; o >>= 1) s += __shfl_xor_sync(0xffffffffu, s, o);
    if (lane == 0) red[w] = s;
    __syncthreads();
    if (tid == 0) bsum = red[0] + red[1] + red[2] + red[3];
    __syncthreads();
    bool wr = (chunk == 0) && (lengths[b] - 1 >= t);
    if (tid < P_) {
        float a = ex0 / bsum;
        al[tid] = a;
        if (wr) out_alphas[(size_t)b * TCAP * P_ + (size_t)t * P_ + tid] = a;
    }
    if (tid + 128 < P_) {
        float a = ex1 / bsum;
        al[tid + 128] = a;
        if (wr) out_alphas[(size_t)b * TCAP * P_ + (size_t)t * P_ + tid + 128] = a;
    }
    __syncthreads();

    // z accumulate: this block handles 128 float4-granules
    int e4 = chunk * 128 + tid;
    const uint2* fp = (const uint2*)(g_feat16 + (size_t)b * P_ * E_) + e4;
    float4 acc = make_float4(0.f, 0.f, 0.f, 0.f);
    #pragma unroll 4
    for (int p = 0; p < P_; p++) {
        float a = al[p];
        uint2 u = fp[(size_t)p * (E_/4)];
        float2 fa = __half22float2(*(__half2*)&u.x);
        float2 fb = __half22float2(*(__half2*)&u.y);
        acc.x += a * fa.x; acc.y += a * fa.y; acc.z += a * fb.x; acc.w += a * fb.y;
    }
    ((float4*)(g_z + (size_t)b * E_))[e4] = acc;
}

// ---------------- GRU cell: sum split parts + biases + masked h update -----
__global__ void k_gru(const float* __restrict__ b_ih, const float* __restrict__ b_hh,
                      const int* __restrict__ lengths, int t) {
    int i = blockIdx.x * 256 + threadIdx.x;   // B*H
    int b = i / H_, j = i % H_;
    size_t base = (size_t)b * 3 * H_;
    float gi_r = b_ih[j],        gi_z = b_ih[H_ + j],        gi_n = b_ih[2*H_ + j];
    #pragma unroll
    for (int s = 0; s < GI_SPLITS; s++) {
        gi_r += g_gip[s][base + j];
        gi_z += g_gip[s][base + H_ + j];
        gi_n += g_gip[s][base + 2*H_ + j];
    }
    float gh_r = g_gh[base + j]        + b_hh[j];
    float gh_z = g_gh[base + H_ + j]   + b_hh[H_ + j];
    float gh_n = g_gh[base + 2*H_ + j] + b_hh[2*H_ + j];
    float r  = fsig(gi_r + gh_r);
    float zg = fsig(gi_z + gh_z);
    float n  = ftanh(gi_n + r * gh_n);
    float h  = g_h[i];
    float hn = (1.f - zg) * n + zg * h;
    if (lengths[b] - 1 >= t) g_h[i] = hn;
}

// ---------------- host driver ----------------------------------------------
extern "C" void kernel_launch(void* const* d_in, const int* in_sizes, int n_in,
                              void* d_out, int out_size) {
    const float* features  = (const float*)d_in[0];
    const int*   captions  = (const int*)  d_in[1];
    const int*   lengths   = (const int*)  d_in[2];
    const float* Wx_w      = (const float*)d_in[3];
    const float* Wx_b      = (const float*)d_in[4];
    const float* Wh_w      = (const float*)d_in[5];
    const float* Wh_b      = (const float*)d_in[6];
    const float* V_w       = (const float*)d_in[7];
    const float* V_b       = (const float*)d_in[8];
    const float* init_h_w  = (const float*)d_in[9];
    const float* init_h_b  = (const float*)d_in[10];
    const float* f_beta_w  = (const float*)d_in[11];
    const float* f_beta_b  = (const float*)d_in[12];
    const float* embed_w   = (const float*)d_in[13];
    const float* gru_w_ih  = (const float*)d_in[14];
    const float* gru_b_ih  = (const float*)d_in[15];
    const float* gru_w_hh  = (const float*)d_in[16];
    const float* gru_b_hh  = (const float*)d_in[17];
    const float* fc1_w     = (const float*)d_in[18];
    const float* fc1_b     = (const float*)d_in[19];
    float* out = (float*)d_out;

    __half *p_xwx;
    float *p_fmean, *p_h;
    cudaGetSymbolAddress((void**)&p_xwx,   g_xwx);
    cudaGetSymbolAddress((void**)&p_fmean, g_fmean);
    cudaGetSymbolAddress((void**)&p_h,     g_h);

    k_zero<<<2048, 256>>>(out, lengths);
    k_feat16<<<(MP_*E_/4)/256, 256>>>(features);
    k_fmean<<<(B_*E_/4)/256, 256>>>(features);
    // h0 = fmean @ init_h^T + b   (N=512, K=2048)
    k_tc64<<<H_/64, 256>>>(p_fmean, init_h_w, init_h_b, p_h,
                           H_, E_, H_, 0, nullptr, 0);
    // x_wx (tensor cores, fp16 out)
    k_gemm_tc<<<dim3(E_/128, MP_/128), 256>>>(features, Wx_w, Wx_b, p_xwx, E_, E_);
    // pre-loop h_wh(0) + gate(0) + gh(0)   (88 blocks, predb=0)
    k_step_fused<<<2*(E_/64) + NB3H, 256>>>(fc1_w, fc1_b, out,
                                            Wh_w, Wh_b, f_beta_w, f_beta_b,
                                            gru_w_hh, lengths, 0, 0);

    for (int t = 0; t < TMAX; t++) {
        // attention scores + softmax/z
        k_lam<<<B_*LAM_BPB, 256>>>(V_w, V_b);
        k_z<<<B_*4, 128>>>(out + PRED_SZ, lengths, t);
        // gi GEMM (TC, split-K x4)
        k_gates_tc<<<NB3H*GI_SPLITS, 256>>>(gru_w_ih, embed_w, captions, t);
        k_gru<<<(B_*H_)/256, 256>>>(gru_b_ih, gru_b_hh, lengths, t);
        // fused: pred(t) + h_wh(t+1) + gate(t+1) + gh(t+1)
        k_step_fused<<<PREDB + 2*(E_/64) + NB3H, 256>>>(fc1_w, fc1_b, out + (size_t)t * V_,
                                                        Wh_w, Wh_b, f_beta_w, f_beta_b,
                                                        gru_w_hh, lengths, t, PREDB);
    }
}